// round 3
// baseline (speedup 1.0000x reference)
#include <cuda_runtime.h>
#include <cuda_bf16.h>
#include <math.h>

// Problem constants (fixed by setup_inputs)
#define B_ROWS   4096
#define T_LEN    3600
#define K_FOLD   900      // folded K (period 1800, +/- fold at 900)
#define K_PAD    928      // 29 * 32
#define N_PAD    512      // even group cols [0,256), odd group cols [256,512)
#define N_GRID   201
#define FMIN     40
#define DELTA    5

// Static device scratch (no allocations allowed)
__device__ float  g_Yt[2][(size_t)K_PAD * B_ROWS];   // [parity][t][b], ~30.4 MB
__device__ float  g_basisT[(size_t)K_PAD * N_PAD];   // [t][n], ~1.9 MB
__device__ float  g_C[(size_t)B_ROWS * N_PAD];       // GEMM output, ~8.4 MB
__device__ double g_acc;

// ---------------------------------------------------------------------------
__global__ void init_kernel() { g_acc = 0.0; }

// Basis: column mapping
//   even group (cols 0..255):  cos at col ge (g=40+2ge, ge<101), sin at col 101+ge; 202..255 zero
//   odd  group (cols 256..511): cos at col 256+go (g=41+2go, go<100), sin at col 356+go; 456..511 zero
__global__ void basis_kernel() {
    int idx = blockIdx.x * 256 + threadIdx.x;
    if (idx >= K_PAD * N_PAD) return;
    int t = idx >> 9;        // / 512
    int n = idx & (N_PAD - 1);
    float v = 0.0f;
    if (t < K_FOLD) {
        int grp = n >> 8;
        int w   = n & 255;
        int g = -1, comp = 0;
        if (grp == 0) {
            if (w < 101)      { g = 40 + 2 * w;         comp = 0; }
            else if (w < 202) { g = 40 + 2 * (w - 101); comp = 1; }
        } else {
            if (w < 100)      { g = 41 + 2 * w;         comp = 0; }
            else if (w < 200) { g = 41 + 2 * (w - 100); comp = 1; }
        }
        if (g >= 0) {
            int r = (g * t) % 1800;   // exact integer phase reduction
            float ang = (float)((double)r * (6.283185307179586476925287 / 1800.0));
            v = comp ? sinf(ang) : cosf(ang);
        }
    }
    g_basisT[idx] = v;
}

// Fold + transpose: x[b][t] -> Yt[p][t][b] (t-major so the GEMM loads coalesced)
__global__ void fold_kernel(const float* __restrict__ x) {
    __shared__ float se[32][33];
    __shared__ float so[32][33];
    int b0 = blockIdx.x * 32;
    int t0 = blockIdx.y * 32;
    int tx = threadIdx.x;   // 0..31
    int ty = threadIdx.y;   // 0..7
    #pragma unroll
    for (int i = 0; i < 32; i += 8) {
        int b = b0 + ty + i;
        int t = t0 + tx;
        float ye = 0.0f, yo = 0.0f;
        if (t < K_FOLD) {
            const float* xr = x + (size_t)b * T_LEN;
            float x0 = xr[t], x1 = xr[t + 900], x2 = xr[t + 1800], x3 = xr[t + 2700];
            float s02 = x0 + x2, s13 = x1 + x3;
            ye = s02 + s13;
            yo = s02 - s13;
        }
        se[ty + i][tx] = ye;
        so[ty + i][tx] = yo;
    }
    __syncthreads();
    #pragma unroll
    for (int i = 0; i < 32; i += 8) {
        int t = t0 + ty + i;
        int b = b0 + tx;
        size_t o = (size_t)t * B_ROWS + b;
        g_Yt[0][o] = se[tx][ty + i];
        g_Yt[1][o] = so[tx][ty + i];
    }
}

// SGEMM: C[4096][512] = Yt[p]^T (M=4096 x K=928) * basisT (K x N=512)
// Tiles: BM=128, BN=128, BK=32; 256 threads, 8x8 micro-tile.
// grid = (32, 4); n-tiles 0..1 -> even parity, 2..3 -> odd.
__global__ void __launch_bounds__(256) gemm_kernel() {
    __shared__ float Ys[32][128];
    __shared__ float Bs[32][128];

    int m0    = blockIdx.x * 128;
    int ntile = blockIdx.y;           // 0..3
    int p     = ntile >> 1;           // parity select of Y
    int n0    = ntile * 128;

    const float* __restrict__ Yb = g_Yt[p];

    int tid = threadIdx.x;
    int tm  = tid & 15;   // m micro position
    int tn  = tid >> 4;   // n micro position
    int lk  = tid >> 5;   // 0..7  (k row for loads)
    int lq  = tid & 31;   // 0..31 (float4 index for loads)

    float acc[8][8];
    #pragma unroll
    for (int i = 0; i < 8; i++)
        #pragma unroll
        for (int j = 0; j < 8; j++) acc[i][j] = 0.0f;

    for (int k0 = 0; k0 < K_PAD; k0 += 32) {
        __syncthreads();
        #pragma unroll
        for (int i = 0; i < 4; i++) {
            int k = lk + i * 8;
            *(float4*)&Ys[k][lq * 4] =
                *(const float4*)&Yb[(size_t)(k0 + k) * B_ROWS + m0 + lq * 4];
            *(float4*)&Bs[k][lq * 4] =
                *(const float4*)&g_basisT[(size_t)(k0 + k) * N_PAD + n0 + lq * 4];
        }
        __syncthreads();
        #pragma unroll
        for (int k = 0; k < 32; k++) {
            float4 a0 = *(float4*)&Ys[k][tm * 4];
            float4 a1 = *(float4*)&Ys[k][tm * 4 + 64];
            float4 b0 = *(float4*)&Bs[k][tn * 4];
            float4 b1 = *(float4*)&Bs[k][tn * 4 + 64];
            float av[8] = {a0.x, a0.y, a0.z, a0.w, a1.x, a1.y, a1.z, a1.w};
            float bv[8] = {b0.x, b0.y, b0.z, b0.w, b1.x, b1.y, b1.z, b1.w};
            #pragma unroll
            for (int i = 0; i < 8; i++)
                #pragma unroll
                for (int j = 0; j < 8; j++)
                    acc[i][j] = fmaf(av[i], bv[j], acc[i][j]);
        }
    }

    #pragma unroll
    for (int i = 0; i < 8; i++) {
        int m = m0 + tm * 4 + (i & 3) + ((i >> 2) * 64);
        #pragma unroll
        for (int j = 0; j < 8; j++) {
            int n = n0 + tn * 4 + (j & 3) + ((j >> 2) * 64);
            g_C[(size_t)m * N_PAD + n] = acc[i][j];
        }
    }
}

// Per-row SNR, accumulate into double
__global__ void reduce_kernel(const int* __restrict__ f_true) {
    int b   = blockIdx.x;
    int tid = threadIdx.x;  // 256
    const float* Cr = g_C + (size_t)b * N_PAD;
    float w = 0.0f, u = 0.0f;
    if (tid < N_GRID) {
        int g = FMIN + tid;
        int ccol, scol;
        if ((g & 1) == 0) { int ge = tid >> 1; ccol = ge;       scol = 101 + ge; }
        else              { int go = tid >> 1; ccol = 256 + go; scol = 356 + go; }
        float a = Cr[ccol];
        float s = Cr[scol];
        float psd = a * a + s * s;
        int d = g - f_true[b];
        if (d < 0) d = -d;
        if (d <= DELTA) w = psd; else u = psd;
    }
    __shared__ float sw[256];
    __shared__ float su[256];
    sw[tid] = w; su[tid] = u;
    __syncthreads();
    for (int off = 128; off > 0; off >>= 1) {
        if (tid < off) { sw[tid] += sw[tid + off]; su[tid] += su[tid + off]; }
        __syncthreads();
    }
    if (tid == 0) {
        float snr = 10.0f * log10f((sw[0] * 190.0f) / (su[0] * 11.0f));
        atomicAdd(&g_acc, (double)snr);
    }
}

__global__ void finalize_kernel(float* out) {
    out[0] = (float)(-g_acc * (1.0 / 4096.0));
}

// ---------------------------------------------------------------------------
extern "C" void kernel_launch(void* const* d_in, const int* in_sizes, int n_in,
                              void* d_out, int out_size) {
    const float* x      = (const float*)d_in[0];
    const int*   f_true = (const int*)d_in[1];
    float*       out    = (float*)d_out;

    init_kernel<<<1, 1>>>();
    basis_kernel<<<(K_PAD * N_PAD + 255) / 256, 256>>>();
    fold_kernel<<<dim3(B_ROWS / 32, K_PAD / 32), dim3(32, 8)>>>(x);
    gemm_kernel<<<dim3(B_ROWS / 128, N_PAD / 128), 256>>>();
    reduce_kernel<<<B_ROWS, 256>>>(f_true);
    finalize_kernel<<<1, 1>>>(out);
}

// round 5
// speedup vs baseline: 1.8611x; 1.8611x over previous
#include <cuda_runtime.h>
#include <cuda_bf16.h>
#include <math.h>
#include <stdint.h>

// ---------------------------------------------------------------------------
// Problem constants
#define B_ROWS   4096
#define T_LEN    3600
#define K_REAL   900        // folded length (period 1800, +/- fold at 900)
#define KP       960        // padded K
#define DELTA    5

// n-tile layout: 4 q-tiles of 128 cols, columns interleaved:
//   col 2u = cos(pair u), col 2u+1 = sin(pair u), freq g = gbase[q] + 2u
//   q=0: even g base 40 (64 pairs), q=1: even base 168 (37 pairs)
//   q=2: odd  g base 41 (64 pairs), q=3: odd  base 169 (36 pairs)
// parity p = q >> 1  (0 = even-g fold, 1 = odd-g fold)

// ---------------------------------------------------------------------------
// Static device scratch
__device__ __nv_bfloat16 g_Yhi[2][(size_t)B_ROWS * KP];   // 15.7 MB
__device__ __nv_bfloat16 g_Ylo[2][(size_t)B_ROWS * KP];   // 15.7 MB
__device__ __nv_bfloat16 g_Bhi[4][(size_t)128 * KP];      // ~1 MB
__device__ __nv_bfloat16 g_Blo[4][(size_t)128 * KP];
__device__ float  g_w[B_ROWS];
__device__ float  g_u[B_ROWS];
__device__ double g_acc;

// ---------------------------------------------------------------------------
__device__ __forceinline__ uint32_t smem_u32(const void* p) {
    uint32_t a;
    asm("{ .reg .u64 t; cvta.to.shared.u64 t, %1; cvt.u32.u64 %0, t; }"
        : "=r"(a) : "l"(p));
    return a;
}
__device__ __forceinline__ void ldsm4(uint32_t& r0, uint32_t& r1,
                                      uint32_t& r2, uint32_t& r3, uint32_t addr) {
    asm volatile("ldmatrix.sync.aligned.m8n8.x4.shared.b16 {%0,%1,%2,%3}, [%4];"
                 : "=r"(r0), "=r"(r1), "=r"(r2), "=r"(r3) : "r"(addr));
}
__device__ __forceinline__ void mma16816(float* d, const uint32_t* a,
                                         uint32_t b0, uint32_t b1) {
    asm volatile(
        "mma.sync.aligned.m16n8k16.row.col.f32.bf16.bf16.f32 "
        "{%0,%1,%2,%3}, {%4,%5,%6,%7}, {%8,%9}, {%0,%1,%2,%3};"
        : "+f"(d[0]), "+f"(d[1]), "+f"(d[2]), "+f"(d[3])
        : "r"(a[0]), "r"(a[1]), "r"(a[2]), "r"(a[3]), "r"(b0), "r"(b1));
}

// ---------------------------------------------------------------------------
__global__ void init_kernel() {
    int i = blockIdx.x * 256 + threadIdx.x;
    if (i < B_ROWS) { g_w[i] = 0.0f; g_u[i] = 0.0f; }
    if (i == 0) g_acc = 0.0;
}

// Basis: hi/lo bf16 split, interleaved cos/sin columns, exact integer phase
__global__ void basis_kernel() {
    int idx = blockIdx.x * 256 + threadIdx.x;
    if (idx >= 4 * 128 * KP) return;
    int q   = idx / (128 * KP);
    int rem = idx - q * 128 * KP;
    int r   = rem / KP;        // column within tile 0..127
    int t   = rem - r * KP;
    int u    = r >> 1;         // pair index
    int comp = r & 1;          // 0 = cos, 1 = sin
    int npairs = (q & 1) ? ((q == 1) ? 37 : 36) : 64;
    int gbase  = (q == 0) ? 40 : (q == 1) ? 168 : (q == 2) ? 41 : 169;
    float v = 0.0f;
    if (u < npairs && t < K_REAL) {
        int g  = gbase + 2 * u;
        int ri = (g * t) % 1800;
        float ang = (float)((double)ri * (6.283185307179586476925287 / 1800.0));
        v = comp ? sinf(ang) : cosf(ang);
    }
    __nv_bfloat16 hi = __float2bfloat16_rn(v);
    __nv_bfloat16 lo = __float2bfloat16_rn(v - __bfloat162float(hi));
    ((__nv_bfloat16*)g_Bhi)[idx] = hi;
    ((__nv_bfloat16*)g_Blo)[idx] = lo;
}

// Fold x[b][t] -> Yhi/Ylo[parity][b][t] bf16 (K-major)
__global__ void fold_kernel(const float* __restrict__ x) {
    int idx = blockIdx.x * 256 + threadIdx.x;
    if (idx >= B_ROWS * (KP / 8)) return;
    int b  = idx / (KP / 8);
    int tc = idx - b * (KP / 8);
    int t0 = tc * 8;
    float ye[8], yo[8];
    const float* xr = x + (size_t)b * T_LEN;
    if (t0 + 7 < K_REAL) {
        #pragma unroll
        for (int h = 0; h < 2; h++) {
            float4 x0 = *(const float4*)(xr + t0 + h * 4);
            float4 x1 = *(const float4*)(xr + t0 + h * 4 + 900);
            float4 x2 = *(const float4*)(xr + t0 + h * 4 + 1800);
            float4 x3 = *(const float4*)(xr + t0 + h * 4 + 2700);
            float s02, s13;
            s02 = x0.x + x2.x; s13 = x1.x + x3.x; ye[h*4+0] = s02 + s13; yo[h*4+0] = s02 - s13;
            s02 = x0.y + x2.y; s13 = x1.y + x3.y; ye[h*4+1] = s02 + s13; yo[h*4+1] = s02 - s13;
            s02 = x0.z + x2.z; s13 = x1.z + x3.z; ye[h*4+2] = s02 + s13; yo[h*4+2] = s02 - s13;
            s02 = x0.w + x2.w; s13 = x1.w + x3.w; ye[h*4+3] = s02 + s13; yo[h*4+3] = s02 - s13;
        }
    } else {
        #pragma unroll
        for (int i = 0; i < 8; i++) {
            int t = t0 + i;
            float e = 0.0f, o = 0.0f;
            if (t < K_REAL) {
                float s02 = xr[t] + xr[t + 1800];
                float s13 = xr[t + 900] + xr[t + 2700];
                e = s02 + s13; o = s02 - s13;
            }
            ye[i] = e; yo[i] = o;
        }
    }
    union { __nv_bfloat16 h[8]; uint4 v; } eh, el, oh, ol;
    #pragma unroll
    for (int i = 0; i < 8; i++) {
        eh.h[i] = __float2bfloat16_rn(ye[i]);
        el.h[i] = __float2bfloat16_rn(ye[i] - __bfloat162float(eh.h[i]));
        oh.h[i] = __float2bfloat16_rn(yo[i]);
        ol.h[i] = __float2bfloat16_rn(yo[i] - __bfloat162float(oh.h[i]));
    }
    size_t o = (size_t)b * KP + t0;
    *(uint4*)(&g_Yhi[0][o]) = eh.v;
    *(uint4*)(&g_Ylo[0][o]) = el.v;
    *(uint4*)(&g_Yhi[1][o]) = oh.v;
    *(uint4*)(&g_Ylo[1][o]) = ol.v;
}

// ---------------------------------------------------------------------------
// mma.sync GEMM + fused PSD/band epilogue.
// CTA: 128x128, BK=32, 256 threads (8 warps, 4M x 2N; warp tile 32x64).
// 3 split terms: Ahi*Bhi + Ahi*Blo + Alo*Bhi, fp32 accumulators.
#define ASTRIDE 40                 // bf16 per SMEM row (80B, conflict-spread)
#define TILE_E  (128 * ASTRIDE)    // bf16 elems per tile
#define NCHUNK  (KP / 32)          // 30 K-chunks

__global__ void __launch_bounds__(256) gemm_mma_kernel(const int* __restrict__ f_true) {
    extern __shared__ __nv_bfloat16 smem[];   // [2 stages][4 tiles][TILE_E]
    const uint32_t smb = smem_u32(smem);

    int tid  = threadIdx.x;
    int wid  = tid >> 5;
    int lane = tid & 31;
    int q  = blockIdx.y;
    int p  = q >> 1;
    int m0 = blockIdx.x * 128;

    const __nv_bfloat16* __restrict__ Ah = g_Yhi[p] + (size_t)m0 * KP;
    const __nv_bfloat16* __restrict__ Al = g_Ylo[p] + (size_t)m0 * KP;
    const __nv_bfloat16* __restrict__ Bh = g_Bhi[q];
    const __nv_bfloat16* __restrict__ Bl = g_Blo[q];

    // global/STS mapping: thread -> (row = tid>>1, 32B half = tid&1)
    int grow = tid >> 1;
    int ghal = tid & 1;
    size_t goff = (size_t)grow * KP + ghal * 16;
    uint32_t soff = (uint32_t)(grow * ASTRIDE + ghal * 16) * 2;  // bytes

    // warp tile
    int mw = (wid >> 1) * 32;   // 0,32,64,96
    int nw = (wid & 1) * 64;    // 0,64

    // ldmatrix per-lane byte offsets (within a tile)
    uint32_t offA = (uint32_t)((mw + (lane & 15)) * ASTRIDE + (lane >> 4) * 8) * 2;
    int bsel = lane >> 3;
    uint32_t offB = (uint32_t)((nw + (bsel >> 1) * 8 + (lane & 7)) * ASTRIDE
                               + (bsel & 1) * 8) * 2;

    float acc[2][8][4];
    #pragma unroll
    for (int i = 0; i < 2; i++)
        #pragma unroll
        for (int j = 0; j < 8; j++)
            #pragma unroll
            for (int c = 0; c < 4; c++) acc[i][j][c] = 0.0f;

    const uint32_t TB = TILE_E * 2;  // tile bytes

    // preload stage 0
    {
        uint4 v;
        v = *(const uint4*)(Ah + goff);      *(uint4*)((char*)smem + 0*TB + soff) = v;
        v = *(const uint4*)(Ah + goff + 8);  *(uint4*)((char*)smem + 0*TB + soff + 16) = v;
        v = *(const uint4*)(Al + goff);      *(uint4*)((char*)smem + 1*TB + soff) = v;
        v = *(const uint4*)(Al + goff + 8);  *(uint4*)((char*)smem + 1*TB + soff + 16) = v;
        v = *(const uint4*)(Bh + goff);      *(uint4*)((char*)smem + 2*TB + soff) = v;
        v = *(const uint4*)(Bh + goff + 8);  *(uint4*)((char*)smem + 2*TB + soff + 16) = v;
        v = *(const uint4*)(Bl + goff);      *(uint4*)((char*)smem + 3*TB + soff) = v;
        v = *(const uint4*)(Bl + goff + 8);  *(uint4*)((char*)smem + 3*TB + soff + 16) = v;
    }
    __syncthreads();

    for (int k = 0; k < NCHUNK; k++) {
        int cur = k & 1;
        uint4 nx[8];
        if (k + 1 < NCHUNK) {
            size_t gk = goff + (k + 1) * 32;
            nx[0] = *(const uint4*)(Ah + gk);  nx[1] = *(const uint4*)(Ah + gk + 8);
            nx[2] = *(const uint4*)(Al + gk);  nx[3] = *(const uint4*)(Al + gk + 8);
            nx[4] = *(const uint4*)(Bh + gk);  nx[5] = *(const uint4*)(Bh + gk + 8);
            nx[6] = *(const uint4*)(Bl + gk);  nx[7] = *(const uint4*)(Bl + gk + 8);
        }

        uint32_t sbase = smb + cur * 4 * TB;
        #pragma unroll
        for (int kk = 0; kk < 32; kk += 16) {
            uint32_t ahi[2][4], alo[2][4];
            #pragma unroll
            for (int mf = 0; mf < 2; mf++) {
                uint32_t ao = offA + (uint32_t)(mf * 16 * ASTRIDE * 2) + kk * 2;
                ldsm4(ahi[mf][0], ahi[mf][1], ahi[mf][2], ahi[mf][3], sbase + 0*TB + ao);
                ldsm4(alo[mf][0], alo[mf][1], alo[mf][2], alo[mf][3], sbase + 1*TB + ao);
            }
            #pragma unroll
            for (int ng = 0; ng < 4; ng++) {
                uint32_t bo = offB + (uint32_t)(ng * 16 * ASTRIDE * 2) + kk * 2;
                uint32_t bh0, bh1, bh2, bh3, bl0, bl1, bl2, bl3;
                ldsm4(bh0, bh1, bh2, bh3, sbase + 2*TB + bo);
                ldsm4(bl0, bl1, bl2, bl3, sbase + 3*TB + bo);
                #pragma unroll
                for (int mf = 0; mf < 2; mf++) {
                    mma16816(acc[mf][ng*2],   ahi[mf], bh0, bh1);
                    mma16816(acc[mf][ng*2+1], ahi[mf], bh2, bh3);
                    mma16816(acc[mf][ng*2],   ahi[mf], bl0, bl1);
                    mma16816(acc[mf][ng*2+1], ahi[mf], bl2, bl3);
                    mma16816(acc[mf][ng*2],   alo[mf], bh0, bh1);
                    mma16816(acc[mf][ng*2+1], alo[mf], bh2, bh3);
                }
            }
        }
        __syncthreads();
        if (k + 1 < NCHUNK) {
            char* st = (char*)smem + ((k + 1) & 1) * 4 * TB;
            *(uint4*)(st + 0*TB + soff)      = nx[0];
            *(uint4*)(st + 0*TB + soff + 16) = nx[1];
            *(uint4*)(st + 1*TB + soff)      = nx[2];
            *(uint4*)(st + 1*TB + soff + 16) = nx[3];
            *(uint4*)(st + 2*TB + soff)      = nx[4];
            *(uint4*)(st + 2*TB + soff + 16) = nx[5];
            *(uint4*)(st + 3*TB + soff)      = nx[6];
            *(uint4*)(st + 3*TB + soff + 16) = nx[7];
            __syncthreads();
        }
    }

    // Fused epilogue: PSD + band sums straight from accumulators.
    // lane holds cols (l%4)*2, +1 -> cos/sin of pair (nw/2 + nf*4 + l%4)
    int gbase = (q == 0) ? 40 : (q == 1) ? 168 : (q == 2) ? 41 : 169;
    #pragma unroll
    for (int mf = 0; mf < 2; mf++) {
        #pragma unroll
        for (int half = 0; half < 2; half++) {
            int row = m0 + mw + mf * 16 + (lane >> 2) + half * 8;
            int f = __ldg(&f_true[row]);
            float w = 0.0f, u = 0.0f;
            #pragma unroll
            for (int nf = 0; nf < 8; nf++) {
                float c = acc[mf][nf][half * 2];
                float s = acc[mf][nf][half * 2 + 1];
                float psd = c * c + s * s;
                int g = gbase + 2 * ((nw >> 1) + nf * 4 + (lane & 3));
                int d = g - f; if (d < 0) d = -d;
                if (d <= DELTA) w += psd; else u += psd;
            }
            w += __shfl_xor_sync(0xFFFFFFFFu, w, 1);
            w += __shfl_xor_sync(0xFFFFFFFFu, w, 2);
            u += __shfl_xor_sync(0xFFFFFFFFu, u, 1);
            u += __shfl_xor_sync(0xFFFFFFFFu, u, 2);
            if ((lane & 3) == 0) {
                atomicAdd(&g_w[row], w);
                atomicAdd(&g_u[row], u);
            }
        }
    }
}

// Per-row SNR -> mean
__global__ void reduce_kernel() {
    int r = blockIdx.x * 256 + threadIdx.x;
    float snr = 0.0f;
    if (r < B_ROWS)
        snr = 10.0f * log10f((g_w[r] * 190.0f) / (g_u[r] * 11.0f));
    __shared__ float sh[256];
    sh[threadIdx.x] = snr;
    __syncthreads();
    for (int off = 128; off > 0; off >>= 1) {
        if (threadIdx.x < off) sh[threadIdx.x] += sh[threadIdx.x + off];
        __syncthreads();
    }
    if (threadIdx.x == 0) atomicAdd(&g_acc, (double)sh[0]);
}

__global__ void finalize_kernel(float* out) {
    out[0] = (float)(-g_acc * (1.0 / 4096.0));
}

// ---------------------------------------------------------------------------
extern "C" void kernel_launch(void* const* d_in, const int* in_sizes, int n_in,
                              void* d_out, int out_size) {
    const float* x      = (const float*)d_in[0];
    const int*   f_true = (const int*)d_in[1];
    float*       out    = (float*)d_out;

    const int GEMM_SMEM = 2 * 4 * TILE_E * 2;   // 81920 bytes
    cudaFuncSetAttribute(gemm_mma_kernel,
                         cudaFuncAttributeMaxDynamicSharedMemorySize, GEMM_SMEM);

    init_kernel<<<(B_ROWS + 255) / 256, 256>>>();
    basis_kernel<<<(4 * 128 * KP + 255) / 256, 256>>>();
    fold_kernel<<<(B_ROWS * (KP / 8) + 255) / 256, 256>>>(x);
    gemm_mma_kernel<<<dim3(B_ROWS / 128, 4), 256, GEMM_SMEM>>>(f_true);
    reduce_kernel<<<B_ROWS / 256, 256>>>();
    finalize_kernel<<<1, 1>>>(out);
}